// round 16
// baseline (speedup 1.0000x reference)
#include <cuda_runtime.h>
#include <cuda_fp16.h>
#include <math.h>
#include <stdint.h>

#define NTOK 4096
#define DMODEL 1024
#define DHID 4096
#define NEXP 8

// ================= scratch (device globals: allocation-free, keep SMALL) =================
__device__ int   g_expert[NTOK];
__device__ float g_gatew[NTOK];
__device__ int   g_counts[NEXP];
__device__ int   g_offsets[NEXP + 1];
__device__ int   g_cursor[NEXP];
__device__ int   g_perm[NTOK];
// grouped hidden, fp16 (32MB)
__device__ __align__(256) __half g_h[(size_t)NTOK * DHID];

__device__ __forceinline__ uint32_t smem_u32(const void* p) {
    uint32_t a;
    asm("{ .reg .u64 t; cvta.to.shared.u64 t, %1; cvt.u32.u64 %0, t; }" : "=r"(a) : "l"(p));
    return a;
}
__device__ __forceinline__ void mma16816(float* d, const uint32_t* a, uint32_t b0, uint32_t b1) {
    asm volatile("mma.sync.aligned.m16n8k16.row.col.f32.f16.f16.f32 "
        "{%0,%1,%2,%3}, {%4,%5,%6,%7}, {%8,%9}, {%0,%1,%2,%3};"
        : "+f"(d[0]), "+f"(d[1]), "+f"(d[2]), "+f"(d[3])
        : "r"(a[0]), "r"(a[1]), "r"(a[2]), "r"(a[3]), "r"(b0), "r"(b1));
}
__device__ __forceinline__ void ldsm_x4(uint32_t a, uint32_t& r0, uint32_t& r1,
                                        uint32_t& r2, uint32_t& r3) {
    asm volatile("ldmatrix.sync.aligned.m8n8.x4.shared.b16 {%0,%1,%2,%3}, [%4];"
        : "=r"(r0), "=r"(r1), "=r"(r2), "=r"(r3) : "r"(a));
}
__device__ __forceinline__ void ldsm_x4t(uint32_t a, uint32_t& r0, uint32_t& r1,
                                         uint32_t& r2, uint32_t& r3) {
    asm volatile("ldmatrix.sync.aligned.m8n8.x4.trans.shared.b16 {%0,%1,%2,%3}, [%4];"
        : "=r"(r0), "=r"(r1), "=r"(r2), "=r"(r3) : "r"(a));
}
__device__ __forceinline__ uint32_t pack_h2(float f0, float f1) {
    __half2 h = __floats2half2_rn(f0, f1);
    return *(uint32_t*)&h;
}

// ================= gating / routing (R1-proven) =================
__global__ void k_zero() {
    int t = threadIdx.x;
    if (t < NEXP) { g_counts[t] = 0; g_cursor[t] = 0; }
}
__global__ void k_gate(const float* __restrict__ x, const float* __restrict__ Wg,
                       const float* __restrict__ bg) {
    int tok = blockIdx.x * 8 + (threadIdx.x >> 5);
    int lane = threadIdx.x & 31;
    if (tok >= NTOK) return;
    float acc[NEXP];
#pragma unroll
    for (int e = 0; e < NEXP; e++) acc[e] = 0.f;
    const float* xr = x + (size_t)tok * DMODEL;
    for (int d = lane; d < DMODEL; d += 32) {
        float xv = xr[d];
        const float* wr = Wg + d * NEXP;
#pragma unroll
        for (int e = 0; e < NEXP; e++) acc[e] += xv * wr[e];
    }
#pragma unroll
    for (int e = 0; e < NEXP; e++)
#pragma unroll
        for (int o = 16; o > 0; o >>= 1) acc[e] += __shfl_xor_sync(0xffffffffu, acc[e], o);
    if (lane == 0) {
        float m = -1e30f; int arg = 0;
#pragma unroll
        for (int e = 0; e < NEXP; e++) {
            float l = acc[e] + bg[e]; acc[e] = l;
            if (l > m) { m = l; arg = e; }   // strict > : first-index argmax like jnp
        }
        float s = 0.f;
#pragma unroll
        for (int e = 0; e < NEXP; e++) s += expf(acc[e] - m);
        g_expert[tok] = arg;
        g_gatew[tok] = 1.0f / s;
        atomicAdd(&g_counts[arg], 1);
    }
}
__global__ void k_scan() {
    if (threadIdx.x == 0) {
        int acc = 0; g_offsets[0] = 0;
        for (int e = 0; e < NEXP; e++) {
            acc += g_counts[e];
            g_offsets[e + 1] = acc;
            g_cursor[e] = g_offsets[e];
        }
    }
}
__global__ void k_scatter() {
    int tok = blockIdx.x * blockDim.x + threadIdx.x;
    if (tok >= NTOK) return;
    int slot = atomicAdd(&g_cursor[g_expert[tok]], 1);
    g_perm[slot] = tok;
}

// ================= fp16 HMMA grouped GEMM: 128-thread CTAs, BM=128 x BN=64 =================
// 4 warps (4m x 1n), warp tile 32x64 (same per-warp shape as R15). 4 CTAs/SM.
// A smem: 128 rows(m) x 32 k fp16, 80B stride, non-trans ldsm.
// B smem: 32 rows(k) x 64 n fp16, 144B stride (36 words = 4 mod 32: conflict-free trans ldsm).
// BK=32, 2 stages, register-prefetch staging packed at load, 1 syncthreads/stage.
#define AROWB 80
#define BROWB 144
#define AOFF 0
#define BOFF 10240
#define TSTAGE 14848

template <bool IS2>
__global__ __launch_bounds__(128, 4) void k_ffn_mma(const float* __restrict__ W,
                                                    const float* __restrict__ bias,
                                                    const float* __restrict__ x,
                                                    float* __restrict__ y) {
    constexpr int K  = IS2 ? DHID : DMODEL;
    constexpr int NN = IS2 ? DMODEL : DHID;
    constexpr int S  = K / 32;

    __shared__ __align__(128) char smemc[2 * TSTAGE];

    int e = blockIdx.z;
    int off = g_offsets[e];
    int cnt = g_offsets[e + 1] - off;
    int row0 = blockIdx.y * 128;
    if (row0 >= cnt) return;
    int col0 = blockIdx.x * 64;

    int tid = threadIdx.x, lane = tid & 31, wid = tid >> 5;
    int wm = wid;                     // 4 m-warps, 1 n-warp
    int g = lane >> 2, q = lane & 3;
    uint32_t sb = smem_u32(smemc);

    // ---- A staging: one row per thread (row = tid), 32 k ----
    int aslot = off + row0 + tid; if (aslot > NTOK - 1) aslot = NTOK - 1;
    const float* ax = nullptr;
    const __half* ah = nullptr;
    if (IS2) ah = g_h + (size_t)aslot * DHID;
    else     ax = x + (size_t)g_perm[aslot] * DMODEL;
    uint32_t asm_off = (uint32_t)(tid * AROWB);

    // ---- B staging: k = (tid>>4) + 8j, n4 = (tid&15)*4 (coalesced float4) ----
    int kb0 = tid >> 4;               // 0..7
    int n4 = (tid & 15) * 4;          // 0..60
    const float* bwp = W + (size_t)e * K * NN + col0 + n4;
    uint32_t bsm_base = (uint32_t)(kb0 * BROWB + n4 * 2);

    // ---- ldmatrix lane offsets ----
    uint32_t arel[2];
#pragma unroll
    for (int mt = 0; mt < 2; mt++) {
        int r = wm * 32 + mt * 16 + (lane & 7) + 8 * ((lane >> 3) & 1);
        arel[mt] = (uint32_t)(r * AROWB + (lane >> 4) * 16);
    }
    uint32_t brel[4];
#pragma unroll
    for (int p = 0; p < 4; p++) {
        int kl = lane & 15;
        int nc = p * 16 + (lane >> 4) * 8;
        brel[p] = (uint32_t)(kl * BROWB + nc * 2);
    }

    float acc[2][8][4];
#pragma unroll
    for (int i = 0; i < 2; i++)
#pragma unroll
        for (int j = 0; j < 8; j++)
#pragma unroll
            for (int p = 0; p < 4; p++) acc[i][j][p] = 0.f;

    // staging registers (pre-packed fp16 words)
    uint32_t apk[16];   // A: 32 fp16 (one row)
    uint32_t bpk[8];    // B: 16 fp16

#define LDG_STAGE(GI) do {                                                     \
        int kk = (GI) * 32;                                                    \
        if (IS2) {                                                             \
            uint4 u0 = *(const uint4*)(ah + kk);                               \
            uint4 u1 = *(const uint4*)(ah + kk + 8);                           \
            uint4 u2 = *(const uint4*)(ah + kk + 16);                          \
            uint4 u3 = *(const uint4*)(ah + kk + 24);                          \
            apk[0]=u0.x; apk[1]=u0.y; apk[2]=u0.z; apk[3]=u0.w;                \
            apk[4]=u1.x; apk[5]=u1.y; apk[6]=u1.z; apk[7]=u1.w;                \
            apk[8]=u2.x; apk[9]=u2.y; apk[10]=u2.z; apk[11]=u2.w;              \
            apk[12]=u3.x; apk[13]=u3.y; apk[14]=u3.z; apk[15]=u3.w;            \
        } else {                                                               \
            _Pragma("unroll")                                                  \
            for (int j = 0; j < 8; j++) {                                      \
                float4 f = *(const float4*)(ax + kk + j * 4);                  \
                apk[j * 2 + 0] = pack_h2(f.x, f.y);                            \
                apk[j * 2 + 1] = pack_h2(f.z, f.w);                            \
            }                                                                  \
        }                                                                      \
        _Pragma("unroll")                                                      \
        for (int j = 0; j < 4; j++) {                                          \
            float4 f = *(const float4*)(bwp + (size_t)(kk + kb0 + 8 * j) * NN);\
            bpk[j * 2 + 0] = pack_h2(f.x, f.y);                                \
            bpk[j * 2 + 1] = pack_h2(f.z, f.w);                                \
        }                                                                      \
    } while (0)

#define STORE_STAGE(BUF) do {                                                  \
        char* s_ = smemc + (BUF) * TSTAGE;                                     \
        _Pragma("unroll")                                                      \
        for (int j = 0; j < 4; j++) {                                          \
            uint4 u_;                                                          \
            u_.x = apk[j*4+0]; u_.y = apk[j*4+1];                              \
            u_.z = apk[j*4+2]; u_.w = apk[j*4+3];                              \
            *(uint4*)(s_ + AOFF + asm_off + j * 16) = u_;                      \
        }                                                                      \
        _Pragma("unroll")                                                      \
        for (int j = 0; j < 4; j++) {                                          \
            uint2 b_;                                                          \
            b_.x = bpk[j * 2 + 0]; b_.y = bpk[j * 2 + 1];                      \
            *(uint2*)(s_ + BOFF + bsm_base + j * 8 * BROWB) = b_;              \
        }                                                                      \
    } while (0)

    // prologue
    LDG_STAGE(0);
    STORE_STAGE(0);
    LDG_STAGE(1);
    __syncthreads();

    for (int gi = 0; gi < S; gi++) {
        uint32_t sbuf = sb + (uint32_t)(gi & 1) * TSTAGE;
        // ---- compute stage gi: two k16 slices ----
#pragma unroll
        for (int k16 = 0; k16 < 2; k16++) {
            uint32_t af[2][4];
#pragma unroll
            for (int mt = 0; mt < 2; mt++)
                ldsm_x4(sbuf + AOFF + arel[mt] + k16 * 32,
                        af[mt][0], af[mt][1], af[mt][2], af[mt][3]);
#pragma unroll
            for (int p = 0; p < 4; p++) {
                uint32_t b0, b1, b2, b3;
                ldsm_x4t(sbuf + BOFF + brel[p] + (uint32_t)(k16 * 16 * BROWB),
                         b0, b1, b2, b3);
                int n0 = p * 2, n1 = p * 2 + 1;
                mma16816(acc[0][n0], af[0], b0, b1);
                mma16816(acc[1][n0], af[1], b0, b1);
                mma16816(acc[0][n1], af[0], b2, b3);
                mma16816(acc[1][n1], af[1], b2, b3);
            }
        }
        // ---- stage gi+1 store, stage gi+2 prefetch ----
        if (gi + 1 < S) STORE_STAGE((gi + 1) & 1);
        if (gi + 2 < S) LDG_STAGE(gi + 2);
        __syncthreads();
    }
#undef LDG_STAGE
#undef STORE_STAGE

    // ================= epilogue =================
    const float* be_ = bias + (size_t)e * NN;
    int q2 = q * 2;
#pragma unroll
    for (int mt = 0; mt < 2; mt++) {
#pragma unroll
        for (int half = 0; half < 2; half++) {
            int ml = wm * 32 + mt * 16 + g + half * 8;
            if (row0 + ml >= cnt) continue;
            int slot = off + row0 + ml;
            if (!IS2) {
                __half* hrow = g_h + (size_t)slot * DHID;
#pragma unroll
                for (int nt8 = 0; nt8 < 8; nt8++) {
                    int cg = col0 + nt8 * 8 + q2;
                    float z0 = acc[mt][nt8][half * 2 + 0] + be_[cg];
                    float z1 = acc[mt][nt8][half * 2 + 1] + be_[cg + 1];
                    float s0 = z0 / (1.f + expf(-z0));
                    float s1 = z1 / (1.f + expf(-z1));
                    *(uint32_t*)(hrow + cg) = pack_h2(s0, s1);
                }
            } else {
                int tok = g_perm[slot];
                float gw = g_gatew[tok];
                float* yrow = y + (size_t)tok * DMODEL;
#pragma unroll
                for (int nt8 = 0; nt8 < 8; nt8++) {
                    int cg = col0 + nt8 * 8 + q2;
                    float2 o;
                    o.x = (acc[mt][nt8][half * 2 + 0] + be_[cg]) * gw;
                    o.y = (acc[mt][nt8][half * 2 + 1] + be_[cg + 1]) * gw;
                    *(float2*)(yrow + cg) = o;
                }
            }
        }
    }
}

// ================= launch =================
extern "C" void kernel_launch(void* const* d_in, const int* in_sizes, int n_in,
                              void* d_out, int out_size) {
    const float* x  = (const float*)d_in[0];
    const float* Wg = (const float*)d_in[1];
    const float* bg = (const float*)d_in[2];
    const float* W1 = (const float*)d_in[3];
    const float* b1 = (const float*)d_in[4];
    const float* W2 = (const float*)d_in[5];
    const float* b2 = (const float*)d_in[6];
    float* y = (float*)d_out;

    k_zero<<<1, 32>>>();
    k_gate<<<NTOK / 8, 256>>>(x, Wg, bg);
    k_scan<<<1, 1>>>();
    k_scatter<<<NTOK / 256, 256>>>();
    k_ffn_mma<false><<<dim3(DHID / 64, NTOK / 128, NEXP), 128>>>(W1, b1, x, nullptr);
    k_ffn_mma<true ><<<dim3(DMODEL / 64, NTOK / 128, NEXP), 128>>>(W2, b2, x, y);
}

// round 17
// speedup vs baseline: 1.6726x; 1.6726x over previous
#include <cuda_runtime.h>
#include <cuda_fp16.h>
#include <math.h>
#include <stdint.h>

#define NTOK 4096
#define DMODEL 1024
#define DHID 4096
#define NEXP 8

// ================= scratch (device globals: allocation-free, keep SMALL) =================
__device__ int   g_expert[NTOK];
__device__ float g_gatew[NTOK];
__device__ int   g_counts[NEXP];
__device__ int   g_offsets[NEXP + 1];
__device__ int   g_cursor[NEXP];
__device__ int   g_perm[NTOK];
// grouped hidden, fp16 (32MB)
__device__ __align__(256) __half g_h[(size_t)NTOK * DHID];

__device__ __forceinline__ uint32_t smem_u32(const void* p) {
    uint32_t a;
    asm("{ .reg .u64 t; cvta.to.shared.u64 t, %1; cvt.u32.u64 %0, t; }" : "=r"(a) : "l"(p));
    return a;
}
__device__ __forceinline__ void mma16816(float* d, const uint32_t* a, uint32_t b0, uint32_t b1) {
    asm volatile("mma.sync.aligned.m16n8k16.row.col.f32.f16.f16.f32 "
        "{%0,%1,%2,%3}, {%4,%5,%6,%7}, {%8,%9}, {%0,%1,%2,%3};"
        : "+f"(d[0]), "+f"(d[1]), "+f"(d[2]), "+f"(d[3])
        : "r"(a[0]), "r"(a[1]), "r"(a[2]), "r"(a[3]), "r"(b0), "r"(b1));
}
__device__ __forceinline__ void ldsm_x4(uint32_t a, uint32_t& r0, uint32_t& r1,
                                        uint32_t& r2, uint32_t& r3) {
    asm volatile("ldmatrix.sync.aligned.m8n8.x4.shared.b16 {%0,%1,%2,%3}, [%4];"
        : "=r"(r0), "=r"(r1), "=r"(r2), "=r"(r3) : "r"(a));
}
__device__ __forceinline__ void ldsm_x4t(uint32_t a, uint32_t& r0, uint32_t& r1,
                                         uint32_t& r2, uint32_t& r3) {
    asm volatile("ldmatrix.sync.aligned.m8n8.x4.trans.shared.b16 {%0,%1,%2,%3}, [%4];"
        : "=r"(r0), "=r"(r1), "=r"(r2), "=r"(r3) : "r"(a));
}
__device__ __forceinline__ uint32_t pack_h2(float f0, float f1) {
    __half2 h = __floats2half2_rn(f0, f1);
    return *(uint32_t*)&h;
}

// ================= gating / routing (R1-proven) =================
__global__ void k_zero() {
    int t = threadIdx.x;
    if (t < NEXP) { g_counts[t] = 0; g_cursor[t] = 0; }
}
__global__ void k_gate(const float* __restrict__ x, const float* __restrict__ Wg,
                       const float* __restrict__ bg) {
    int tok = blockIdx.x * 8 + (threadIdx.x >> 5);
    int lane = threadIdx.x & 31;
    if (tok >= NTOK) return;
    float acc[NEXP];
#pragma unroll
    for (int e = 0; e < NEXP; e++) acc[e] = 0.f;
    const float* xr = x + (size_t)tok * DMODEL;
    for (int d = lane; d < DMODEL; d += 32) {
        float xv = xr[d];
        const float* wr = Wg + d * NEXP;
#pragma unroll
        for (int e = 0; e < NEXP; e++) acc[e] += xv * wr[e];
    }
#pragma unroll
    for (int e = 0; e < NEXP; e++)
#pragma unroll
        for (int o = 16; o > 0; o >>= 1) acc[e] += __shfl_xor_sync(0xffffffffu, acc[e], o);
    if (lane == 0) {
        float m = -1e30f; int arg = 0;
#pragma unroll
        for (int e = 0; e < NEXP; e++) {
            float l = acc[e] + bg[e]; acc[e] = l;
            if (l > m) { m = l; arg = e; }   // strict > : first-index argmax like jnp
        }
        float s = 0.f;
#pragma unroll
        for (int e = 0; e < NEXP; e++) s += expf(acc[e] - m);
        g_expert[tok] = arg;
        g_gatew[tok] = 1.0f / s;
        atomicAdd(&g_counts[arg], 1);
    }
}
__global__ void k_scan() {
    if (threadIdx.x == 0) {
        int acc = 0; g_offsets[0] = 0;
        for (int e = 0; e < NEXP; e++) {
            acc += g_counts[e];
            g_offsets[e + 1] = acc;
            g_cursor[e] = g_offsets[e];
        }
    }
}
__global__ void k_scatter() {
    int tok = blockIdx.x * blockDim.x + threadIdx.x;
    if (tok >= NTOK) return;
    int slot = atomicAdd(&g_cursor[g_expert[tok]], 1);
    g_perm[slot] = tok;
}

// ================= fp16 HMMA grouped GEMM, BK=32, trans-B, 4-buffer ring =================
// Tiles and layout identical to R15 (proven): A 128x32 @80B stride non-trans ldsm;
// B 32x128 @272B stride ldsm.x4.trans. 4 stage-buffers, ONE __syncthreads per 2 stages.
// Window (stages gi,gi+1): STORE(gi+2) LDG(gi+3) compute(gi) STORE(gi+3) LDG(gi+4)
// compute(gi+1) sync. 8 warps (4M x 2N), warp tile 32x64.
#define AROWB 80
#define BROWB 272
#define AOFF 0
#define BOFF 10240
#define TSTAGE 18944
#define SMEM_DYN (4 * TSTAGE)

template <bool IS2>
__global__ __launch_bounds__(256, 2) void k_ffn_mma(const float* __restrict__ W,
                                                    const float* __restrict__ bias,
                                                    const float* __restrict__ x,
                                                    float* __restrict__ y) {
    constexpr int K  = IS2 ? DHID : DMODEL;
    constexpr int NN = IS2 ? DMODEL : DHID;
    constexpr int S  = K / 32;   // even (32 or 128)

    extern __shared__ __align__(128) char smemc[];

    int e = blockIdx.z;
    int off = g_offsets[e];
    int cnt = g_offsets[e + 1] - off;
    int row0 = blockIdx.y * 128;
    if (row0 >= cnt) return;
    int col0 = blockIdx.x * 128;

    int tid = threadIdx.x, lane = tid & 31, wid = tid >> 5;
    int wm = wid & 3, wn = wid >> 2;
    int g = lane >> 2, q = lane & 3;
    uint32_t sb = smem_u32(smemc);

    // ---- A staging: row = tid>>1 (128 rows), kc = tid&1 (16-elem half of k32) ----
    int arw = tid >> 1, kc = tid & 1;
    int aslot = off + row0 + arw; if (aslot > NTOK - 1) aslot = NTOK - 1;
    const float* ax = nullptr;
    const __half* ah = nullptr;
    if (IS2) ah = g_h + (size_t)aslot * DHID + kc * 16;
    else     ax = x + (size_t)g_perm[aslot] * DMODEL + kc * 16;
    uint32_t asm_off = (uint32_t)(arw * AROWB + kc * 32);

    // ---- B staging: coalesced. k = kb0+8j, n4 = lane*4 ----
    int kb0 = tid >> 5;           // 0..7
    int n4 = lane * 4;            // 0..124
    const float* bwp = W + (size_t)e * K * NN + col0 + n4;
    uint32_t bsm_base = (uint32_t)(kb0 * BROWB + n4 * 2);

    // ---- ldmatrix lane offsets ----
    uint32_t arel[2];
#pragma unroll
    for (int mt = 0; mt < 2; mt++) {
        int r = wm * 32 + mt * 16 + (lane & 7) + 8 * ((lane >> 3) & 1);
        arel[mt] = (uint32_t)(r * AROWB + (lane >> 4) * 16);
    }
    uint32_t brel[4];
#pragma unroll
    for (int p = 0; p < 4; p++) {
        int kl = lane & 15;
        int nc = wn * 64 + p * 16 + (lane >> 4) * 8;
        brel[p] = (uint32_t)(kl * BROWB + nc * 2);
    }

    float acc[2][8][4];
#pragma unroll
    for (int i = 0; i < 2; i++)
#pragma unroll
        for (int j = 0; j < 8; j++)
#pragma unroll
            for (int p = 0; p < 4; p++) acc[i][j][p] = 0.f;

    // staging registers
    float4 fa[4];          // FFN1 A: 16 fp32
    uint4  uah[2];         // FFN2 A: 16 fp16
    float4 fbv[4];         // B: 4x coalesced float4

#define LDG_STAGE(GI) do {                                                     \
        int kk = (GI) * 32;                                                    \
        if (IS2) {                                                             \
            uah[0] = *(const uint4*)(ah + kk);                                 \
            uah[1] = *(const uint4*)(ah + kk + 8);                             \
        } else {                                                               \
            fa[0] = *(const float4*)(ax + kk);                                 \
            fa[1] = *(const float4*)(ax + kk + 4);                             \
            fa[2] = *(const float4*)(ax + kk + 8);                             \
            fa[3] = *(const float4*)(ax + kk + 12);                            \
        }                                                                      \
        _Pragma("unroll")                                                      \
        for (int j = 0; j < 4; j++)                                            \
            fbv[j] = *(const float4*)(bwp + (size_t)(kk + kb0 + 8 * j) * NN);  \
    } while (0)

#define STORE_STAGE(BUF) do {                                                  \
        char* s_ = smemc + (BUF) * TSTAGE;                                     \
        if (IS2) {                                                             \
            *(uint4*)(s_ + AOFF + asm_off) = uah[0];                           \
            *(uint4*)(s_ + AOFF + asm_off + 16) = uah[1];                      \
        } else {                                                               \
            uint4 h_;                                                          \
            h_.x = pack_h2(fa[0].x, fa[0].y);                                  \
            h_.y = pack_h2(fa[0].z, fa[0].w);                                  \
            h_.z = pack_h2(fa[1].x, fa[1].y);                                  \
            h_.w = pack_h2(fa[1].z, fa[1].w);                                  \
            *(uint4*)(s_ + AOFF + asm_off) = h_;                               \
            h_.x = pack_h2(fa[2].x, fa[2].y);                                  \
            h_.y = pack_h2(fa[2].z, fa[2].w);                                  \
            h_.z = pack_h2(fa[3].x, fa[3].y);                                  \
            h_.w = pack_h2(fa[3].z, fa[3].w);                                  \
            *(uint4*)(s_ + AOFF + asm_off + 16) = h_;                          \
        }                                                                      \
        _Pragma("unroll")                                                      \
        for (int j = 0; j < 4; j++) {                                          \
            uint2 b_;                                                          \
            b_.x = pack_h2(fbv[j].x, fbv[j].y);                                \
            b_.y = pack_h2(fbv[j].z, fbv[j].w);                                \
            *(uint2*)(s_ + BOFF + bsm_base + j * 8 * BROWB) = b_;              \
        }                                                                      \
    } while (0)

#define COMPUTE(BUF) do {                                                      \
        uint32_t sbuf_ = sb + (uint32_t)(BUF) * TSTAGE;                        \
        _Pragma("unroll")                                                      \
        for (int k16 = 0; k16 < 2; k16++) {                                    \
            uint32_t af[2][4];                                                 \
            _Pragma("unroll")                                                  \
            for (int mt = 0; mt < 2; mt++)                                     \
                ldsm_x4(sbuf_ + AOFF + arel[mt] + k16 * 32,                    \
                        af[mt][0], af[mt][1], af[mt][2], af[mt][3]);           \
            _Pragma("unroll")                                                  \
            for (int p = 0; p < 4; p++) {                                      \
                uint32_t b0, b1, b2, b3;                                       \
                ldsm_x4t(sbuf_ + BOFF + brel[p] + (uint32_t)(k16 * 16 * BROWB),\
                         b0, b1, b2, b3);                                      \
                int n0 = p * 2, n1 = p * 2 + 1;                                \
                mma16816(acc[0][n0], af[0], b0, b1);                           \
                mma16816(acc[1][n0], af[1], b0, b1);                           \
                mma16816(acc[0][n1], af[0], b2, b3);                           \
                mma16816(acc[1][n1], af[1], b2, b3);                           \
            }                                                                  \
        }                                                                      \
    } while (0)

    // prologue: buffers 0,1 filled; regs hold stage 2
    LDG_STAGE(0); STORE_STAGE(0);
    LDG_STAGE(1); STORE_STAGE(1);
    if (S > 2) LDG_STAGE(2);
    __syncthreads();

    for (int gi = 0; gi < S; gi += 2) {
        if (gi + 2 < S) STORE_STAGE((gi + 2) & 3);
        if (gi + 3 < S) LDG_STAGE(gi + 3);
        COMPUTE(gi & 3);
        if (gi + 3 < S) STORE_STAGE((gi + 3) & 3);
        if (gi + 4 < S) LDG_STAGE(gi + 4);
        COMPUTE((gi + 1) & 3);
        __syncthreads();
    }
#undef LDG_STAGE
#undef STORE_STAGE
#undef COMPUTE

    // ================= epilogue =================
    const float* be_ = bias + (size_t)e * NN;
    int q2 = q * 2;
#pragma unroll
    for (int mt = 0; mt < 2; mt++) {
#pragma unroll
        for (int half = 0; half < 2; half++) {
            int ml = wm * 32 + mt * 16 + g + half * 8;
            if (row0 + ml >= cnt) continue;
            int slot = off + row0 + ml;
            if (!IS2) {
                __half* hrow = g_h + (size_t)slot * DHID;
#pragma unroll
                for (int nt8 = 0; nt8 < 8; nt8++) {
                    int cg = col0 + wn * 64 + nt8 * 8 + q2;
                    float z0 = acc[mt][nt8][half * 2 + 0] + be_[cg];
                    float z1 = acc[mt][nt8][half * 2 + 1] + be_[cg + 1];
                    float s0 = z0 / (1.f + expf(-z0));
                    float s1 = z1 / (1.f + expf(-z1));
                    *(uint32_t*)(hrow + cg) = pack_h2(s0, s1);
                }
            } else {
                int tok = g_perm[slot];
                float gw = g_gatew[tok];
                float* yrow = y + (size_t)tok * DMODEL;
#pragma unroll
                for (int nt8 = 0; nt8 < 8; nt8++) {
                    int cg = col0 + wn * 64 + nt8 * 8 + q2;
                    float2 o;
                    o.x = (acc[mt][nt8][half * 2 + 0] + be_[cg]) * gw;
                    o.y = (acc[mt][nt8][half * 2 + 1] + be_[cg + 1]) * gw;
                    *(float2*)(yrow + cg) = o;
                }
            }
        }
    }
}

// ================= launch =================
extern "C" void kernel_launch(void* const* d_in, const int* in_sizes, int n_in,
                              void* d_out, int out_size) {
    const float* x  = (const float*)d_in[0];
    const float* Wg = (const float*)d_in[1];
    const float* bg = (const float*)d_in[2];
    const float* W1 = (const float*)d_in[3];
    const float* b1 = (const float*)d_in[4];
    const float* W2 = (const float*)d_in[5];
    const float* b2 = (const float*)d_in[6];
    float* y = (float*)d_out;

    cudaFuncSetAttribute(k_ffn_mma<false>, cudaFuncAttributeMaxDynamicSharedMemorySize, SMEM_DYN);
    cudaFuncSetAttribute(k_ffn_mma<true>,  cudaFuncAttributeMaxDynamicSharedMemorySize, SMEM_DYN);

    k_zero<<<1, 32>>>();
    k_gate<<<NTOK / 8, 256>>>(x, Wg, bg);
    k_scan<<<1, 1>>>();
    k_scatter<<<NTOK / 256, 256>>>();
    k_ffn_mma<false><<<dim3(DHID / 128, NTOK / 128, NEXP), 256, SMEM_DYN>>>(W1, b1, x, nullptr);
    k_ffn_mma<true ><<<dim3(DMODEL / 128, NTOK / 128, NEXP), 256, SMEM_DYN>>>(W2, b2, x, y);
}